// round 4
// baseline (speedup 1.0000x reference)
#include <cuda_runtime.h>

// CollisionLoss, 8-role version. pos [B=65536, N=24, 3] f32 -> scalar f32.
// Per batch, masked pairs (i<j, i>=1, skip (2,3)):
//   sq = |p_i-p_j|^2 ; if sq < 0.25: sum += exp(-4*sq); cnt++
// out = (cnt>0 ? sum/cnt : 0) + 1e-6
// Coords pre-scaled at staging by s = sqrt(4*log2(e)) so term = 2^(-sq')
// (single EX2) and test is sq' < 1.44269504.
// Block = 256 threads = 8 warps x 32 lanes. lane = batch-in-block, warp = role:
//   w0: tri i in {1..3},  j..12   (29 pairs)     w1: tri i in {4..11}, j..12  (36)
//   w2: tri i in {13..15},j..23   (27)           w3: tri i in {16..22},j..23  (28)
//   w4..w7: cross i in {1..3},{4..6},{7..9},{10..12} x {13..23}  (33 each)
// i-points preloaded to regs; j-point streamed from smem (reused across i's).

#define THREADS 256
#define BATCH_PER_BLOCK 32
#define PTS 24
#define FLOATS_PER (PTS * 3)   // 72
#define SMEM_STRIDE 73         // 73 mod 32 = 9, coprime with 32 -> conflict-free rows
#define MAX_BLOCKS 2048

__device__ float g_psum[MAX_BLOCKS];
__device__ float g_pcnt[MAX_BLOCKS];
__device__ unsigned int g_ticket = 0;

#define PAIR(ax, ay, az, bx, by, bz)                                \
    do {                                                            \
        float d0 = (ax) - (bx);                                     \
        float d1 = (ay) - (by);                                     \
        float d2 = (az) - (bz);                                     \
        float nsq = d0 * -d0;                                       \
        nsq = fmaf(d1, -d1, nsq);                                   \
        nsq = fmaf(d2, -d2, nsq);                                   \
        float e;                                                    \
        asm("ex2.approx.f32 %0, %1;" : "=f"(e) : "f"(nsq));         \
        if (nsq > -1.44269504f) { lsum += e; lcnt += 1; }           \
    } while (0)

// Triangular role: i in [I0, I1] preloaded; j streamed over (I0, JMAX], pairs with i < j.
template <int I0, int I1, int JMAX>
__device__ __forceinline__ void tri_pairs(const float* __restrict__ row,
                                          float& lsum, int& lcnt) {
    const int NI = I1 - I0 + 1;
    float ix[NI], iy[NI], iz[NI];
    #pragma unroll
    for (int k = 0; k < NI; k++) {
        ix[k] = row[(I0 + k) * 3 + 0];
        iy[k] = row[(I0 + k) * 3 + 1];
        iz[k] = row[(I0 + k) * 3 + 2];
    }
    #pragma unroll
    for (int j = I0 + 1; j <= JMAX; j++) {
        float jx = row[j * 3 + 0];
        float jy = row[j * 3 + 1];
        float jz = row[j * 3 + 2];
        #pragma unroll
        for (int k = 0; k < NI; k++) {
            const int i = I0 + k;
            if (i >= j) continue;             // compile-time
            if (i == 2 && j == 3) continue;   // excluded pair, compile-time
            PAIR(ix[k], iy[k], iz[k], jx, jy, jz);
        }
    }
}

// Cross role: i in {I0, I0+1, I0+2} preloaded; j streamed over B = {13..23}.
template <int I0>
__device__ __forceinline__ void cross3(const float* __restrict__ row,
                                       float& lsum, int& lcnt) {
    float ix[3], iy[3], iz[3];
    #pragma unroll
    for (int k = 0; k < 3; k++) {
        ix[k] = row[(I0 + k) * 3 + 0];
        iy[k] = row[(I0 + k) * 3 + 1];
        iz[k] = row[(I0 + k) * 3 + 2];
    }
    #pragma unroll
    for (int j = 13; j <= 23; j++) {
        float jx = row[j * 3 + 0];
        float jy = row[j * 3 + 1];
        float jz = row[j * 3 + 2];
        #pragma unroll
        for (int k = 0; k < 3; k++) {
            PAIR(ix[k], iy[k], iz[k], jx, jy, jz);
        }
    }
}

__global__ __launch_bounds__(THREADS, 6)
void collision_role8_kernel(const float* __restrict__ pos, float* __restrict__ out, int B) {
    __shared__ float sm[BATCH_PER_BLOCK * SMEM_STRIDE];
    __shared__ float wsum[THREADS / 32];
    __shared__ int   wcnt[THREADS / 32];
    __shared__ bool  amLast;

    const int tid   = threadIdx.x;
    const int role  = tid >> 5;          // warp id = role (0..7), warp-uniform
    const int lane  = tid & 31;          // batch within block
    const int bbase = blockIdx.x * BATCH_PER_BLOCK;
    const int valid = min(BATCH_PER_BLOCK, B - bbase);

    // ---- Stage: coalesced float4 gmem -> padded smem, scale folded in ----
    {
        const float SCALE = 2.4022448929611436f;   // sqrt(4 * log2(e))
        const float4* src4 = reinterpret_cast<const float4*>(pos + (size_t)bbase * FLOATS_PER);
        const int n4 = (valid * FLOATS_PER) >> 2;  // 72 % 4 == 0, rows stay intact
        for (int q = tid; q < n4; q += THREADS) {
            float4 v = src4[q];
            int g = q << 2;
            int b = g / FLOATS_PER;
            int w = g - b * FLOATS_PER;
            float* d = &sm[b * SMEM_STRIDE + w];
            d[0] = v.x * SCALE; d[1] = v.y * SCALE;
            d[2] = v.z * SCALE; d[3] = v.w * SCALE;
        }
    }
    __syncthreads();

    float lsum = 0.0f;
    int   lcnt = 0;

    if (lane < valid) {
        const float* row = &sm[lane * SMEM_STRIDE];   // conflict-free across lanes
        switch (role) {
            case 0: tri_pairs<1, 3, 12>(row, lsum, lcnt);  break;  // 29 pairs
            case 1: tri_pairs<4, 11, 12>(row, lsum, lcnt); break;  // 36
            case 2: tri_pairs<13, 15, 23>(row, lsum, lcnt); break; // 27
            case 3: tri_pairs<16, 22, 23>(row, lsum, lcnt); break; // 28
            case 4: cross3<1>(row, lsum, lcnt);  break;            // 33
            case 5: cross3<4>(row, lsum, lcnt);  break;            // 33
            case 6: cross3<7>(row, lsum, lcnt);  break;            // 33
            default: cross3<10>(row, lsum, lcnt); break;           // 33
        }
    }

    // ---- Block reduce ----
    #pragma unroll
    for (int o = 16; o > 0; o >>= 1) {
        lsum += __shfl_down_sync(0xffffffffu, lsum, o);
        lcnt += __shfl_down_sync(0xffffffffu, lcnt, o);
    }
    if (lane == 0) { wsum[role] = lsum; wcnt[role] = lcnt; }
    __syncthreads();
    if (tid == 0) {
        float s = 0.0f; int c = 0;
        #pragma unroll
        for (int w = 0; w < THREADS / 32; w++) { s += wsum[w]; c += wcnt[w]; }
        g_psum[blockIdx.x] = s;
        g_pcnt[blockIdx.x] = (float)c;
        __threadfence();
        unsigned int t = atomicAdd(&g_ticket, 1u);
        amLast = (t == gridDim.x - 1);
    }
    __syncthreads();

    // ---- Last block finalizes ----
    if (amLast) {
        const int nb = gridDim.x;
        float s = 0.0f, c = 0.0f;
        for (int i = tid; i < nb; i += THREADS) {
            s += g_psum[i];
            c += g_pcnt[i];
        }
        #pragma unroll
        for (int o = 16; o > 0; o >>= 1) {
            s += __shfl_down_sync(0xffffffffu, s, o);
            c += __shfl_down_sync(0xffffffffu, c, o);
        }
        if (lane == 0) { wsum[role] = s; wcnt[role] = __float_as_int(c); }
        __syncthreads();
        if (tid == 0) {
            float ts = 0.0f, tc = 0.0f;
            #pragma unroll
            for (int w = 0; w < THREADS / 32; w++) {
                ts += wsum[w];
                tc += __int_as_float(wcnt[w]);
            }
            float total = (tc > 0.0f) ? (ts / fmaxf(tc, 1.0f)) : 0.0f;
            out[0] = total + 1e-6f;
            g_ticket = 0;   // reset for next graph replay
        }
    }
}

extern "C" void kernel_launch(void* const* d_in, const int* in_sizes, int n_in,
                              void* d_out, int out_size) {
    const float* pos = (const float*)d_in[0];
    const int B = in_sizes[0] / FLOATS_PER;
    int nblocks = (B + BATCH_PER_BLOCK - 1) / BATCH_PER_BLOCK;   // 2048 for B=65536
    if (nblocks > MAX_BLOCKS) nblocks = MAX_BLOCKS;
    collision_role8_kernel<<<nblocks, THREADS>>>(pos, (float*)d_out, B);
}

// round 5
// speedup vs baseline: 1.1469x; 1.1469x over previous
#include <cuda_runtime.h>

// CollisionLoss, role-split + BRANCHLESS pair accumulation.
// pos [B=65536, N=24, 3] f32 -> scalar f32.
// Per batch, masked pairs (i<j, i>=1, skip (2,3)):
//   sq = |p_i-p_j|^2 ; if sq < 0.25: sum += exp(-4*sq); cnt++
// out = (cnt>0 ? sum/cnt : 0) + 1e-6
// Coords pre-scaled at staging by s = sqrt(4*log2(e)) so term = 2^(-sq')
// (single EX2) and the test is sq' < 1.44269504.
// KEY CHANGE vs best round: the per-pair `if` is replaced by selects
// (FSETP + FSEL + FADD) — ptxas turns short if-arms into BSSY/BSYNC
// divergence envelopes, which capped issue at ~45% in all prior rounds.

#define THREADS 128
#define BATCH_PER_BLOCK 32
#define PTS 24
#define FLOATS_PER (PTS * 3)   // 72
#define SMEM_STRIDE 73         // 73 mod 32 = 9, coprime with 32 -> conflict-free rows
#define MAX_BLOCKS 2048

__device__ float g_psum[MAX_BLOCKS];
__device__ float g_pcnt[MAX_BLOCKS];
__device__ unsigned int g_ticket = 0;

// Branchless: cond as data, never as a branch.
#define PAIR(ax, ay, az, bx, by, bz)                                 \
    do {                                                             \
        float d0 = (ax) - (bx);                                      \
        float d1 = (ay) - (by);                                      \
        float d2 = (az) - (bz);                                      \
        float nsq = d0 * -d0;                                        \
        nsq = fmaf(d1, -d1, nsq);                                    \
        nsq = fmaf(d2, -d2, nsq);          /* nsq = -scaled_sq */    \
        float e;                                                     \
        asm("ex2.approx.f32 %0, %1;" : "=f"(e) : "f"(nsq));          \
        bool c = (nsq > -1.44269504f);     /* sq < 0.25 */           \
        lsum += c ? e : 0.0f;                                        \
        lcnt += c ? 1.0f : 0.0f;                                     \
    } while (0)

__global__ __launch_bounds__(THREADS, 8)
void collision_bl_kernel(const float* __restrict__ pos, float* __restrict__ out, int B) {
    __shared__ float sm[BATCH_PER_BLOCK * SMEM_STRIDE];
    __shared__ float wsum[THREADS / 32];
    __shared__ float wcnt[THREADS / 32];
    __shared__ bool  amLast;

    const int tid   = threadIdx.x;
    const int role  = tid >> 5;          // warp id = role, warp-uniform
    const int lane  = tid & 31;          // batch within block
    const int bbase = blockIdx.x * BATCH_PER_BLOCK;
    const int valid = min(BATCH_PER_BLOCK, B - bbase);

    // ---- Stage: coalesced float4 gmem -> padded smem, scale folded in ----
    {
        const float SCALE = 2.4022448929611436f;   // sqrt(4 * log2(e))
        const float4* src4 = reinterpret_cast<const float4*>(pos + (size_t)bbase * FLOATS_PER);
        const int n4 = (valid * FLOATS_PER) >> 2;  // 72 % 4 == 0, rows stay intact
        for (int q = tid; q < n4; q += THREADS) {
            float4 v = src4[q];
            int g = q << 2;
            int b = g / FLOATS_PER;
            int w = g - b * FLOATS_PER;
            float* d = &sm[b * SMEM_STRIDE + w];
            d[0] = v.x * SCALE; d[1] = v.y * SCALE;
            d[2] = v.z * SCALE; d[3] = v.w * SCALE;
        }
    }
    __syncthreads();

    float lsum = 0.0f;
    float lcnt = 0.0f;

    if (lane < valid) {
        const float* row = &sm[lane * SMEM_STRIDE];   // conflict-free across lanes

        if (role == 0) {
            // pairs within A = {1..12}, skip (2,3): 65 pairs
            float px[13], py[13], pz[13];
            #pragma unroll
            for (int i = 1; i <= 12; i++) {
                px[i] = row[i * 3 + 0]; py[i] = row[i * 3 + 1]; pz[i] = row[i * 3 + 2];
            }
            #pragma unroll
            for (int i = 1; i <= 12; i++) {
                #pragma unroll
                for (int j = i + 1; j <= 12; j++) {
                    if (i == 2 && j == 3) continue;   // compile-time elided
                    PAIR(px[i], py[i], pz[i], px[j], py[j], pz[j]);
                }
            }
        } else if (role == 1) {
            // pairs within B = {13..23}: 55 pairs
            float px[11], py[11], pz[11];
            #pragma unroll
            for (int j = 0; j < 11; j++) {
                int p = 13 + j;
                px[j] = row[p * 3 + 0]; py[j] = row[p * 3 + 1]; pz[j] = row[p * 3 + 2];
            }
            #pragma unroll
            for (int i = 0; i < 11; i++) {
                #pragma unroll
                for (int j = i + 1; j < 11; j++) {
                    PAIR(px[i], py[i], pz[i], px[j], py[j], pz[j]);
                }
            }
        } else {
            // cross: i-range x B; role2: i in {1..6}, role3: i in {7..12}; 66 pairs each
            float bx[11], by[11], bz[11];
            #pragma unroll
            for (int j = 0; j < 11; j++) {
                int p = 13 + j;
                bx[j] = row[p * 3 + 0]; by[j] = row[p * 3 + 1]; bz[j] = row[p * 3 + 2];
            }
            const int i0 = (role == 2) ? 1 : 7;
            #pragma unroll
            for (int k = 0; k < 6; k++) {
                int i = i0 + k;
                float ax = row[i * 3 + 0];
                float ay = row[i * 3 + 1];
                float az = row[i * 3 + 2];
                #pragma unroll
                for (int j = 0; j < 11; j++) {
                    PAIR(ax, ay, az, bx[j], by[j], bz[j]);
                }
            }
        }
    }

    // ---- Block reduce ----
    #pragma unroll
    for (int o = 16; o > 0; o >>= 1) {
        lsum += __shfl_down_sync(0xffffffffu, lsum, o);
        lcnt += __shfl_down_sync(0xffffffffu, lcnt, o);
    }
    if (lane == 0) { wsum[role] = lsum; wcnt[role] = lcnt; }
    __syncthreads();
    if (tid == 0) {
        float s = 0.0f, c = 0.0f;
        #pragma unroll
        for (int w = 0; w < THREADS / 32; w++) { s += wsum[w]; c += wcnt[w]; }
        g_psum[blockIdx.x] = s;
        g_pcnt[blockIdx.x] = c;
        __threadfence();
        unsigned int t = atomicAdd(&g_ticket, 1u);
        amLast = (t == gridDim.x - 1);
    }
    __syncthreads();

    // ---- Last block finalizes ----
    if (amLast) {
        const int nb = gridDim.x;
        float s = 0.0f, c = 0.0f;
        for (int i = tid; i < nb; i += THREADS) {
            s += g_psum[i];
            c += g_pcnt[i];
        }
        #pragma unroll
        for (int o = 16; o > 0; o >>= 1) {
            s += __shfl_down_sync(0xffffffffu, s, o);
            c += __shfl_down_sync(0xffffffffu, c, o);
        }
        if (lane == 0) { wsum[role] = s; wcnt[role] = c; }
        __syncthreads();
        if (tid == 0) {
            float ts = 0.0f, tc = 0.0f;
            #pragma unroll
            for (int w = 0; w < THREADS / 32; w++) { ts += wsum[w]; tc += wcnt[w]; }
            float total = (tc > 0.0f) ? (ts / fmaxf(tc, 1.0f)) : 0.0f;
            out[0] = total + 1e-6f;
            g_ticket = 0;   // reset for next graph replay
        }
    }
}

extern "C" void kernel_launch(void* const* d_in, const int* in_sizes, int n_in,
                              void* d_out, int out_size) {
    const float* pos = (const float*)d_in[0];
    const int B = in_sizes[0] / FLOATS_PER;
    int nblocks = (B + BATCH_PER_BLOCK - 1) / BATCH_PER_BLOCK;   // 2048 for B=65536
    if (nblocks > MAX_BLOCKS) nblocks = MAX_BLOCKS;
    collision_bl_kernel<<<nblocks, THREADS>>>(pos, (float*)d_out, B);
}

// round 6
// speedup vs baseline: 1.6294x; 1.4207x over previous
#include <cuda_runtime.h>

// CollisionLoss, f32x2-packed: each thread computes 2 batches (lo/hi halves
// of packed 64-bit f32x2 registers), halving the core FP instruction count.
// pos [B=65536, N=24, 3] f32 -> scalar f32.
// Per batch, masked pairs (i<j, i>=1, skip (2,3)):
//   sq = |p_i-p_j|^2 ; if sq < 0.25: sum += exp(-4*sq); cnt++
// out = (cnt>0 ? sum/cnt : 0) + 1e-6
// Coords pre-scaled at staging by s = sqrt(4*log2(e)) so term = 2^(-sq')
// (one EX2 with folded negate) and the test is sq' < 1.44269504.
// Block: 128 thr = 4 role-warps x 32 lanes; lane L handles batches (b, b+32).
// Roles (i preloaded <=4 pts, j streamed via LDS.64):
//   w0: i{1..3} (62 pairs)  w1: i{4..7} (70)
//   w2: i{8..11}+{19..22} (64)  w3: i{12..15}+{16..18} (56)

typedef unsigned long long u64;

#define THREADS 128
#define FLOATS_PER 72
#define ROW_F2 73                 // float2 cells per lane row (72 + 1 pad)
#define BATCHES_PER_BLOCK 64
#define MAX_BLOCKS 2048

__device__ float g_psum[MAX_BLOCKS];
__device__ float g_pcnt[MAX_BLOCKS];
__device__ unsigned int g_ticket = 0;

__device__ __forceinline__ u64 f2_mul(u64 a, u64 b) {
    u64 d; asm("mul.rn.f32x2 %0, %1, %2;" : "=l"(d) : "l"(a), "l"(b)); return d;
}
__device__ __forceinline__ u64 f2_fma(u64 a, u64 b, u64 c) {
    u64 d; asm("fma.rn.f32x2 %0, %1, %2, %3;" : "=l"(d) : "l"(a), "l"(b), "l"(c)); return d;
}
__device__ __forceinline__ float nex2(float s) {   // 2^(-s), neg folds into MUFU
    float e;
    asm("{\n\t.reg .f32 t;\n\tneg.f32 t, %1;\n\tex2.approx.f32 %0, t;\n\t}"
        : "=f"(e) : "f"(s));
    return e;
}

#define NEG1_F32X2 0xBF800000BF800000ULL

// One packed pair: 2 real pairs (lo batch + hi batch).
#define PAIR2(ix_, iy_, iz_, jx_, jy_, jz_)                           \
    do {                                                              \
        u64 d0 = f2_fma((jx_), NEG1, (ix_));   /* i - j */            \
        u64 d1 = f2_fma((jy_), NEG1, (iy_));                          \
        u64 d2 = f2_fma((jz_), NEG1, (iz_));                          \
        u64 s2 = f2_mul(d0, d0);                                      \
        s2 = f2_fma(d1, d1, s2);                                      \
        s2 = f2_fma(d2, d2, s2);           /* scaled sq, positive */  \
        float sl, sh;                                                 \
        asm("mov.b64 {%0, %1}, %2;" : "=f"(sl), "=f"(sh) : "l"(s2));  \
        float el = nex2(sl);                                          \
        float eh = nex2(sh);                                          \
        float wl = (sl < 1.44269504f) ? 1.0f : 0.0f;                  \
        float wh = (sh < 1.44269504f) ? 1.0f : 0.0f;                  \
        sum_lo = fmaf(el, wl, sum_lo);  cnt_lo += wl;                 \
        sum_hi = fmaf(eh, wh, sum_hi);  cnt_hi += wh;                 \
    } while (0)

// i in [I0, I1] preloaded packed; j streamed over (I0, 23]; pairs with i<j,
// (2,3) excluded at compile time.
template <int I0, int I1>
__device__ __forceinline__ void tri_stream(const u64* __restrict__ row, u64 NEG1,
                                           float& sum_lo, float& sum_hi,
                                           float& cnt_lo, float& cnt_hi) {
    const int NI = I1 - I0 + 1;
    u64 ix[NI], iy[NI], iz[NI];
    #pragma unroll
    for (int k = 0; k < NI; k++) {
        ix[k] = row[(I0 + k) * 3 + 0];
        iy[k] = row[(I0 + k) * 3 + 1];
        iz[k] = row[(I0 + k) * 3 + 2];
    }
    #pragma unroll
    for (int j = I0 + 1; j <= 23; j++) {
        u64 jx = row[j * 3 + 0];
        u64 jy = row[j * 3 + 1];
        u64 jz = row[j * 3 + 2];
        #pragma unroll
        for (int k = 0; k < NI; k++) {
            const int i = I0 + k;
            if (i >= j) continue;             // compile-time
            if (i == 2 && j == 3) continue;   // excluded pair, compile-time
            PAIR2(ix[k], iy[k], iz[k], jx, jy, jz);
        }
    }
}

__global__ __launch_bounds__(THREADS, 8)
void collision_f32x2_kernel(const float* __restrict__ pos, float* __restrict__ out, int B) {
    __shared__ float smf[32 * ROW_F2 * 2];      // 32 lanes x 73 float2 cells
    __shared__ float wsum[THREADS / 32];
    __shared__ float wcnt[THREADS / 32];
    __shared__ bool  amLast;

    const int tid   = threadIdx.x;
    const int role  = tid >> 5;
    const int lane  = tid & 31;
    const int bbase = blockIdx.x * BATCHES_PER_BLOCK;
    const int nvalid = min(BATCHES_PER_BLOCK, B - bbase);

    // ---- Stage: coalesced float4 gmem -> interleaved (lo,hi) float2 smem ----
    // Batch bl (0..63) -> lane = bl&31, half = bl>>5. Coord word w lives at
    // float index (lane*ROW_F2 + w)*2 + half. Invalid region staged as zeros
    // (gated out at the end by validity selects).
    {
        const float SCALE = 2.4022448929611436f;   // sqrt(4 * log2(e))
        const float4* src4 = reinterpret_cast<const float4*>(pos + (size_t)bbase * FLOATS_PER);
        const int n4 = nvalid * 18;                // valid float4 count
        for (int q = tid; q < BATCHES_PER_BLOCK * 18; q += THREADS) {
            float4 v = make_float4(0.f, 0.f, 0.f, 0.f);
            if (q < n4) v = src4[q];
            int bl = q / 18;
            int w4 = q - bl * 18;
            int ln = bl & 31, half = bl >> 5;
            float* d = &smf[((ln * ROW_F2 + (w4 << 2)) << 1) + half];
            d[0] = v.x * SCALE; d[2] = v.y * SCALE;
            d[4] = v.z * SCALE; d[6] = v.w * SCALE;
        }
    }
    __syncthreads();

    const u64 NEG1 = NEG1_F32X2;
    float sum_lo = 0.0f, sum_hi = 0.0f, cnt_lo = 0.0f, cnt_hi = 0.0f;

    {
        const u64* row = reinterpret_cast<const u64*>(&smf[lane * ROW_F2 * 2]);
        if (role == 0) {
            tri_stream<1, 3>(row, NEG1, sum_lo, sum_hi, cnt_lo, cnt_hi);    // 62
        } else if (role == 1) {
            tri_stream<4, 7>(row, NEG1, sum_lo, sum_hi, cnt_lo, cnt_hi);    // 70
        } else if (role == 2) {
            tri_stream<8, 11>(row, NEG1, sum_lo, sum_hi, cnt_lo, cnt_hi);   // 54
            tri_stream<19, 22>(row, NEG1, sum_lo, sum_hi, cnt_lo, cnt_hi);  // 10
        } else {
            tri_stream<12, 15>(row, NEG1, sum_lo, sum_hi, cnt_lo, cnt_hi);  // 38
            tri_stream<16, 18>(row, NEG1, sum_lo, sum_hi, cnt_lo, cnt_hi);  // 18
        }
    }

    // Validity gating (selects, so NaN/zero-padded halves can't leak in).
    const bool vlo = (bbase + lane) < B;
    const bool vhi = (bbase + 32 + lane) < B;
    float lsum = (vlo ? sum_lo : 0.0f) + (vhi ? sum_hi : 0.0f);
    float lcnt = (vlo ? cnt_lo : 0.0f) + (vhi ? cnt_hi : 0.0f);

    // ---- Block reduce ----
    #pragma unroll
    for (int o = 16; o > 0; o >>= 1) {
        lsum += __shfl_down_sync(0xffffffffu, lsum, o);
        lcnt += __shfl_down_sync(0xffffffffu, lcnt, o);
    }
    if (lane == 0) { wsum[role] = lsum; wcnt[role] = lcnt; }
    __syncthreads();
    if (tid == 0) {
        float s = 0.0f, c = 0.0f;
        #pragma unroll
        for (int w = 0; w < THREADS / 32; w++) { s += wsum[w]; c += wcnt[w]; }
        g_psum[blockIdx.x] = s;
        g_pcnt[blockIdx.x] = c;
        __threadfence();
        unsigned int t = atomicAdd(&g_ticket, 1u);
        amLast = (t == gridDim.x - 1);
    }
    __syncthreads();

    // ---- Last block finalizes ----
    if (amLast) {
        const int nb = gridDim.x;
        float s = 0.0f, c = 0.0f;
        for (int i = tid; i < nb; i += THREADS) {
            s += g_psum[i];
            c += g_pcnt[i];
        }
        #pragma unroll
        for (int o = 16; o > 0; o >>= 1) {
            s += __shfl_down_sync(0xffffffffu, s, o);
            c += __shfl_down_sync(0xffffffffu, c, o);
        }
        if (lane == 0) { wsum[role] = s; wcnt[role] = c; }
        __syncthreads();
        if (tid == 0) {
            float ts = 0.0f, tc = 0.0f;
            #pragma unroll
            for (int w = 0; w < THREADS / 32; w++) { ts += wsum[w]; tc += wcnt[w]; }
            float total = (tc > 0.0f) ? (ts / fmaxf(tc, 1.0f)) : 0.0f;
            out[0] = total + 1e-6f;
            g_ticket = 0;   // reset for next graph replay
        }
    }
}

extern "C" void kernel_launch(void* const* d_in, const int* in_sizes, int n_in,
                              void* d_out, int out_size) {
    const float* pos = (const float*)d_in[0];
    const int B = in_sizes[0] / FLOATS_PER;
    int nblocks = (B + BATCHES_PER_BLOCK - 1) / BATCHES_PER_BLOCK;   // 1024 for B=65536
    if (nblocks > MAX_BLOCKS) nblocks = MAX_BLOCKS;
    collision_f32x2_kernel<<<nblocks, THREADS>>>(pos, (float*)d_out, B);
}